// round 8
// baseline (speedup 1.0000x reference)
#include <cuda_runtime.h>
#include <cuda_bf16.h>
#include <stdint.h>

// Problem dims
#define T_STEPS 100
#define BATCH   512
#define NI      784          // = 49 * 16
#define NH      1024
#define NO      10
#define M_TOT   (T_STEPS * BATCH)   // 51200
#define NIT     49                   // K chunks of 16

// Certification bound on |cur1_tc - cur1_ref| (elementwise, generous)
#define EPS_C   4e-4f

// ---------------------------------------------------------------------------
// Scratch (static __device__ arrays: allocation-free per harness rules)
// ---------------------------------------------------------------------------
__device__ float          g_cur1[(size_t)M_TOT * NH];    // 210 MB
__device__ unsigned char  g_spk1[(size_t)M_TOT * NH];    // 52 MB
__device__ float          g_cur2[(size_t)M_TOT * NO];    // 2 MB
__device__ __align__(16) unsigned short g_wa1[(size_t)NH * NI];
__device__ __align__(16) unsigned short g_wa2[(size_t)NH * NI];
__device__ int g_bcnt[BATCH];                 // flagged count per batch row
__device__ int g_flagn[BATCH * NH];           // flagged n-list per batch row

// chained mma: c += a*b
__device__ __forceinline__ void mma_bf16(float* c, const uint32_t* a, const uint32_t* b) {
    asm volatile(
        "mma.sync.aligned.m16n8k16.row.col.f32.bf16.bf16.f32 "
        "{%0,%1,%2,%3}, {%4,%5,%6,%7}, {%8,%9}, {%0,%1,%2,%3};"
        : "+f"(c[0]), "+f"(c[1]), "+f"(c[2]), "+f"(c[3])
        : "r"(a[0]), "r"(a[1]), "r"(a[2]), "r"(a[3]), "r"(b[0]), "r"(b[1]));
}

// isolated mma: d = a*b + z (z = constant zero)
__device__ __forceinline__ void mma_bf16_z(float* d, const uint32_t* a, const uint32_t* b,
                                           const float* z) {
    asm volatile(
        "mma.sync.aligned.m16n8k16.row.col.f32.bf16.bf16.f32 "
        "{%0,%1,%2,%3}, {%4,%5,%6,%7}, {%8,%9}, {%10,%11,%12,%13};"
        : "=f"(d[0]), "=f"(d[1]), "=f"(d[2]), "=f"(d[3])
        : "r"(a[0]), "r"(a[1]), "r"(a[2]), "r"(a[3]), "r"(b[0]), "r"(b[1]),
          "f"(z[0]), "f"(z[1]), "f"(z[2]), "f"(z[3]));
}

// 2-term split: (va, vb) -> packed bf16x2 h1 (ret) and h2 (out)
__device__ __forceinline__ uint32_t pack_split2(float va, float vb, uint32_t& p2) {
    __nv_bfloat16 a1 = __float2bfloat16_rn(va);
    __nv_bfloat16 a2 = __float2bfloat16_rn(va - __bfloat162float(a1));
    __nv_bfloat16 b1 = __float2bfloat16_rn(vb);
    __nv_bfloat16 b2 = __float2bfloat16_rn(vb - __bfloat162float(b1));
    p2 = (uint32_t)__bfloat16_as_ushort(a2) | ((uint32_t)__bfloat16_as_ushort(b2) << 16);
    return (uint32_t)__bfloat16_as_ushort(a1) | ((uint32_t)__bfloat16_as_ushort(b1) << 16);
}

// ---------------------------------------------------------------------------
// Split kernel for W1 (2-term) + zero the flag counters
// ---------------------------------------------------------------------------
__global__ __launch_bounds__(256) void k_split_w(const float* __restrict__ w) {
    if (blockIdx.x < 2) {
        int z = blockIdx.x * 256 + threadIdx.x;
        if (z < BATCH) g_bcnt[z] = 0;
    }
    size_t i = (size_t)blockIdx.x * 256 + threadIdx.x;
    if (i >= (size_t)NH * NI) return;
    float v = w[i];
    __nv_bfloat16 h1 = __float2bfloat16_rn(v);
    __nv_bfloat16 h2 = __float2bfloat16_rn(v - __bfloat162float(h1));
    g_wa1[i] = __bfloat16_as_ushort(h1);
    g_wa2[i] = __bfloat16_as_ushort(h2);
}

// ---------------------------------------------------------------------------
// Kernel A: 2-split bf16 mma GEMM (certified-precision engine).
//   big (h1*w1): isolated mma per chunk (zero C), drained into fp32 csum.
//   corr (h1*w2 + h2*w1): chained in separate small accumulator.
// CTA tile 128x64, 8 warps (2x4 -> warp 64x16), K-chunk 16.
// ---------------------------------------------------------------------------
#define TILESB  6144                 // 128 * 48 (A tiles)
#define BTILESB 3072                 // 64 * 48  (B tiles)

__global__ __launch_bounds__(256, 1) void k_gemm1_v5(const float* __restrict__ X,
                                                     const float* __restrict__ bias) {
    __shared__ __align__(16) char sbuf[2 * TILESB + 2 * BTILESB];   // 18.4 KB

    const int tid = threadIdx.x;
    const int wid = tid >> 5;
    const int lid = tid & 31;
    const int g = lid >> 2;
    const int t = lid & 3;

    const int m0 = blockIdx.y * 128;
    const int n0 = blockIdx.x * 64;
    const int m_off = (wid & 1) * 64;
    const int n_off = (wid >> 1) * 16;

    char* const Abase = sbuf;
    char* const Bbase = sbuf + 2 * TILESB;

    const int br = tid >> 1;
    const int bh = tid & 1;

    uint4 pa[2];
    uint4 pb[2];

    {
#pragma unroll
        for (int q = 0; q < 2; q++) {
            int idx = q * 256 + tid;
            int r = idx >> 2, c4 = idx & 3;
            pa[q] = *(const uint4*)(X + (size_t)(m0 + r) * NI + c4 * 4);
        }
        if (tid < 128) {
            pb[0] = *(const uint4*)(g_wa1 + (size_t)(n0 + br) * NI + bh * 8);
            pb[1] = *(const uint4*)(g_wa2 + (size_t)(n0 + br) * NI + bh * 8);
        }
    }

    float csum[4][2][4];
    float corr[4][2][4];
    float zr[4] = {0.0f, 0.0f, 0.0f, 0.0f};
#pragma unroll
    for (int mf = 0; mf < 4; mf++)
#pragma unroll
        for (int nf = 0; nf < 2; nf++)
#pragma unroll
            for (int q = 0; q < 4; q++) { csum[mf][nf][q] = 0.0f; corr[mf][nf][q] = 0.0f; }

    for (int it = 0; it < NIT; it++) {
        __syncthreads();

#pragma unroll
        for (int q = 0; q < 2; q++) {
            int idx = q * 256 + tid;
            int r = idx >> 2, c4 = idx & 3;
            float f0 = __uint_as_float(pa[q].x);
            float f1 = __uint_as_float(pa[q].y);
            float f2 = __uint_as_float(pa[q].z);
            float f3 = __uint_as_float(pa[q].w);
            uint32_t s2a, s2b;
            uint32_t s1a = pack_split2(f0, f1, s2a);
            uint32_t s1b = pack_split2(f2, f3, s2b);
            char* p = Abase + r * 48 + c4 * 8;
            *(uint2*)(p)          = make_uint2(s1a, s1b);
            *(uint2*)(p + TILESB) = make_uint2(s2a, s2b);
        }
        if (tid < 128) {
            char* p = Bbase + br * 48 + bh * 16;
            *(uint4*)(p)           = pb[0];
            *(uint4*)(p + BTILESB) = pb[1];
        }
        __syncthreads();

        if (it + 1 < NIT) {
            const int k0 = (it + 1) * 16;
#pragma unroll
            for (int q = 0; q < 2; q++) {
                int idx = q * 256 + tid;
                int r = idx >> 2, c4 = idx & 3;
                pa[q] = *(const uint4*)(X + (size_t)(m0 + r) * NI + k0 + c4 * 4);
            }
            if (tid < 128) {
                pb[0] = *(const uint4*)(g_wa1 + (size_t)(n0 + br) * NI + k0 + bh * 8);
                pb[1] = *(const uint4*)(g_wa2 + (size_t)(n0 + br) * NI + k0 + bh * 8);
            }
        }

        uint32_t bfr[2][2][2];
#pragma unroll
        for (int s = 0; s < 2; s++) {
            const char* Bt = Bbase + s * BTILESB;
#pragma unroll
            for (int nf = 0; nf < 2; nf++) {
                const char* p = Bt + (n_off + nf * 8 + g) * 48 + 4 * t;
                bfr[s][nf][0] = *(const uint32_t*)(p);
                bfr[s][nf][1] = *(const uint32_t*)(p + 16);
            }
        }

        float big[4][2][4];
#pragma unroll
        for (int mf = 0; mf < 4; mf++) {
            uint32_t af[2][4];
#pragma unroll
            for (int s = 0; s < 2; s++) {
                const char* At = Abase + s * TILESB;
                const char* p0 = At + (m_off + mf * 16 + g) * 48 + 4 * t;
                const char* p1 = At + (m_off + mf * 16 + g + 8) * 48 + 4 * t;
                af[s][0] = *(const uint32_t*)(p0);
                af[s][1] = *(const uint32_t*)(p1);
                af[s][2] = *(const uint32_t*)(p0 + 16);
                af[s][3] = *(const uint32_t*)(p1 + 16);
            }
#pragma unroll
            for (int nf = 0; nf < 2; nf++) {
                mma_bf16_z(big[mf][nf], af[0], bfr[0][nf], zr);   // h1*w1 isolated
                mma_bf16(corr[mf][nf], af[0], bfr[1][nf]);        // h1*w2
                mma_bf16(corr[mf][nf], af[1], bfr[0][nf]);        // h2*w1
            }
        }

#pragma unroll
        for (int mf = 0; mf < 4; mf++)
#pragma unroll
            for (int nf = 0; nf < 2; nf++)
#pragma unroll
                for (int q = 0; q < 4; q++)
                    csum[mf][nf][q] += big[mf][nf][q];
    }

#pragma unroll
    for (int mf = 0; mf < 4; mf++) {
        const int row = m0 + m_off + mf * 16 + g;
#pragma unroll
        for (int nf = 0; nf < 2; nf++) {
            const int col = n0 + n_off + nf * 8 + 2 * t;
            float2 bv = *(const float2*)(bias + col);
            float2 v0, v1;
            v0.x = (csum[mf][nf][0] + corr[mf][nf][0]) + bv.x;
            v0.y = (csum[mf][nf][1] + corr[mf][nf][1]) + bv.y;
            v1.x = (csum[mf][nf][2] + corr[mf][nf][2]) + bv.x;
            v1.y = (csum[mf][nf][3] + corr[mf][nf][3]) + bv.y;
            *(float2*)(g_cur1 + (size_t)row * NH + col) = v0;
            *(float2*)(g_cur1 + (size_t)(row + 8) * NH + col) = v1;
        }
    }
}

// ---------------------------------------------------------------------------
// Kernel B: layer-1 INTERVAL scan. Propagates [lo,hi] for cur1 +- EPS_C.
// Certified neurons keep provisional spikes; straddling neurons are flagged
// per batch row for exact recompute.
// ---------------------------------------------------------------------------
__global__ __launch_bounds__(256) void k_scan1_cert() {
    int idx = blockIdx.x * 256 + threadIdx.x;   // b*NH + n
    const size_t stride = (size_t)BATCH * NH;
    float lo = 0.0f, hi = 0.0f;
    int flagged = 0;
    for (int t = 0; t < T_STEPS; t++) {
        float c = g_cur1[(size_t)t * stride + idx];
        bool rlo = lo > 1.0f, rhi = hi > 1.0f;
        if (rlo != rhi) {
            flagged = 1;
            float m = 0.5f * (lo + hi);
            lo = hi = m;
            rlo = rhi = (m > 1.0f);
        }
        lo = 0.9f * lo + (c - EPS_C) - (rlo ? 1.0f : 0.0f);
        hi = 0.9f * hi + (c + EPS_C) - (rhi ? 1.0f : 0.0f);
        bool slo = lo > 1.0f, shi = hi > 1.0f;
        if (slo != shi) {
            flagged = 1;
            float m = 0.5f * (lo + hi);
            lo = hi = m;
            shi = (m > 1.0f);
        }
        g_spk1[(size_t)t * stride + idx] = shi ? (unsigned char)1 : (unsigned char)0;
    }
    if (flagged) {
        int b = idx >> 10;          // NH = 1024
        int n = idx & (NH - 1);
        int slot = atomicAdd(&g_bcnt[b], 1);
        g_flagn[(b << 10) + slot] = n;
    }
}

// ---------------------------------------------------------------------------
// Kernel B2: exact recompute of flagged neurons. One CTA per batch row b.
// x[t,b,:] staged in smem once per t per neuron-batch; W rows in registers;
// fp32 warp-reduced dots (round-1 numerics) + exact rescan, overwriting spk1.
// ---------------------------------------------------------------------------
__global__ __launch_bounds__(256) void k_fix(const float* __restrict__ X,
                                             const float* __restrict__ W1,
                                             const float* __restrict__ b1) {
    __shared__ float xs[800];   // 784 + zero pad
    const int b = blockIdx.x;
    const int cnt = g_bcnt[b];
    if (cnt == 0) return;
    const int wid = threadIdx.x >> 5;
    const int lane = threadIdx.x & 31;
    const size_t stride = (size_t)BATCH * NH;

    for (int base = 0; base < cnt; base += 32) {   // 8 warps x 4 neurons
        int   nn[4];
        float wreg[4][25];
        float mem[4];
        float bb[4];
#pragma unroll
        for (int i = 0; i < 4; i++) {
            int li = base + wid * 4 + i;
            if (li < cnt) {
                int n = g_flagn[(b << 10) + li];
                nn[i] = n;
                bb[i] = b1[n];
                mem[i] = 0.0f;
#pragma unroll
                for (int j = 0; j < 25; j++) {
                    int k = lane + 32 * j;
                    wreg[i][j] = (k < NI) ? W1[(size_t)n * NI + k] : 0.0f;
                }
            } else {
                nn[i] = -1;
            }
        }

        for (int t = 0; t < T_STEPS; t++) {
            __syncthreads();
            for (int k = threadIdx.x; k < 800; k += 256)
                xs[k] = (k < NI) ? X[((size_t)t * BATCH + b) * NI + k] : 0.0f;
            __syncthreads();
#pragma unroll
            for (int i = 0; i < 4; i++) {
                if (nn[i] < 0) continue;
                float s = 0.0f;
#pragma unroll
                for (int j = 0; j < 25; j++)
                    s += wreg[i][j] * xs[lane + 32 * j];
#pragma unroll
                for (int o = 16; o > 0; o >>= 1)
                    s += __shfl_xor_sync(0xFFFFFFFFu, s, o);
                if (lane == 0) {
                    float reset = (mem[i] > 1.0f) ? 1.0f : 0.0f;
                    mem[i] = 0.9f * mem[i] + (s + bb[i]) - reset;
                    g_spk1[(size_t)t * stride + (b << 10) + nn[i]] =
                        (mem[i] > 1.0f) ? (unsigned char)1 : (unsigned char)0;
                }
            }
        }
    }
}

// ---------------------------------------------------------------------------
// Kernel C: cur2[tb,j] = sum_n spk1[tb,n]*W2[j,n] + b2[j]
// ---------------------------------------------------------------------------
__global__ __launch_bounds__(128) void k_gemm2(const float* __restrict__ W2,
                                               const float* __restrict__ b2) {
    __shared__ float         w2s[NO * NH];
    __shared__ unsigned char sp[128 * 36];

    int tid = threadIdx.x;
    int tb0 = blockIdx.x * 128;

    const float4* w2g = (const float4*)W2;
    float4* w2s4 = (float4*)w2s;
#pragma unroll
    for (int i = tid; i < (NO * NH) / 4; i += 128) w2s4[i] = w2g[i];

    float acc[NO];
#pragma unroll
    for (int j = 0; j < NO; j++) acc[j] = 0.0f;

    for (int kc = 0; kc < NH / 32; kc++) {
        __syncthreads();
#pragma unroll
        for (int i = 0; i < 8; i++) {
            int lin = i * 128 + tid;
            int r = lin >> 3;
            int c = lin & 7;
            uint32_t v = *(const uint32_t*)(g_spk1 + (size_t)(tb0 + r) * NH + kc * 32 + c * 4);
            *(uint32_t*)(sp + r * 36 + c * 4) = v;
        }
        __syncthreads();

        const uint32_t* myrow = (const uint32_t*)(sp + tid * 36);
#pragma unroll
        for (int q = 0; q < 8; q++) {
            uint32_t v = myrow[q];
            float s0 = (float)(v & 1u);
            float s1 = (float)((v >> 8) & 1u);
            float s2 = (float)((v >> 16) & 1u);
            float s3 = (float)((v >> 24) & 1u);
            int fidx = kc * 8 + q;
#pragma unroll
            for (int j = 0; j < NO; j++) {
                float4 w = ((const float4*)(w2s + j * NH))[fidx];
                acc[j] += s0 * w.x;
                acc[j] += s1 * w.y;
                acc[j] += s2 * w.z;
                acc[j] += s3 * w.w;
            }
        }
    }

#pragma unroll
    for (int j = 0; j < NO; j++)
        g_cur2[(size_t)(tb0 + tid) * NO + j] = acc[j] + __ldg(&b2[j]);
}

// ---------------------------------------------------------------------------
// Kernel D: layer-2 leaky scan; writes spk2_rec then final mem2.
// ---------------------------------------------------------------------------
__global__ __launch_bounds__(256) void k_scan2(float* __restrict__ out) {
    __shared__ float sc[25][256];
    int idx = blockIdx.x * 256 + threadIdx.x;
    const int stride = BATCH * NO;
    float m = 0.0f;
    for (int tc = 0; tc < 4; tc++) {
        __syncthreads();
#pragma unroll
        for (int j = 0; j < 25; j++)
            sc[j][threadIdx.x] = g_cur2[(size_t)(tc * 25 + j) * stride + idx];
        __syncthreads();
#pragma unroll
        for (int j = 0; j < 25; j++) {
            int t = tc * 25 + j;
            float c = sc[j][threadIdx.x];
            float reset = (m > 1.0f) ? 1.0f : 0.0f;
            m = 0.9f * m + c - reset;
            out[(size_t)t * stride + idx] = (m > 1.0f) ? 1.0f : 0.0f;
        }
    }
    out[(size_t)T_STEPS * stride + idx] = m;
}

// ---------------------------------------------------------------------------
extern "C" void kernel_launch(void* const* d_in, const int* in_sizes, int n_in,
                              void* d_out, int out_size) {
    const float* x  = (const float*)d_in[0];   // [T,B,NI]
    const float* W1 = (const float*)d_in[1];   // [NH,NI]
    const float* b1 = (const float*)d_in[2];   // [NH]
    const float* W2 = (const float*)d_in[3];   // [NO,NH]
    const float* b2 = (const float*)d_in[4];   // [NO]
    float* out = (float*)d_out;

    // 0: 2-term bf16 split of W1 + zero flag counters
    k_split_w<<<(NH * NI + 255) / 256, 256>>>(W1);

    // A: tensor-core GEMM cur1 = x @ W1^T + b1 (certified-precision engine)
    dim3 gridA(NH / 64, M_TOT / 128);   // (16, 400)
    k_gemm1_v5<<<gridA, 256>>>(x, b1);

    // B: interval scan -> provisional spikes + flags
    k_scan1_cert<<<(BATCH * NH) / 256, 256>>>();

    // B2: exact recompute of flagged neurons (overwrites their spikes)
    k_fix<<<BATCH, 256>>>(x, W1, b1);

    // C: cur2 = spk1 @ W2^T + b2
    k_gemm2<<<M_TOT / 128, 128>>>(W2, b2);

    // D: layer-2 scan -> output spikes + final mem2
    k_scan2<<<(BATCH * NO) / 256, 256>>>(out);
}

// round 10
// speedup vs baseline: 2.7063x; 2.7063x over previous
#include <cuda_runtime.h>
#include <stdint.h>

// Problem dims
#define T_STEPS 100
#define BATCH   512
#define NI      784
#define NH      1024
#define NO      10
#define M_TOT   (T_STEPS * BATCH)   // 51200

// Scratch (static __device__ arrays: allocation-free per harness rules)
__device__ float          g_cur1[(size_t)M_TOT * NH];   // ~210 MB
__device__ unsigned char  g_spk1[(size_t)M_TOT * NH];   // ~52 MB
__device__ float          g_cur2[(size_t)M_TOT * NO];   // ~2 MB

typedef unsigned long long ull;

// packed dual fp32 FMA: c = a*b + c on two independent lanes (RN each lane)
__device__ __forceinline__ void ffma2(ull& c, ull a, ull b) {
    asm("fma.rn.f32x2 %0, %1, %2, %0;" : "+l"(c) : "l"(a), "l"(b));
}
__device__ __forceinline__ ull dup2(float v) {
    ull r;
    asm("mov.b64 %0, {%1, %1};" : "=l"(r) : "f"(v));
    return r;
}

// ---------------------------------------------------------------------------
// Kernel A: cur1[m,n] = sum_k X[m,k]*W1[n,k] + b1[n]
// Round-1 SGEMM skeleton (128x128x16, 256 thr, 8x8 microtile) with the inner
// product executed as fma.rn.f32x2: accumulators paired along m, A-operand
// pairs loaded directly as b64 from smem, B scalars duplicated per k.
// Per-scalar-accumulator operation sequence is IDENTICAL to round 1
// (same k order, RN fp32 FMA) -> bit-identical cur1.
// ---------------------------------------------------------------------------
__global__ __launch_bounds__(256, 2) void k_gemm1(const float* __restrict__ X,
                                                  const float* __restrict__ W1,
                                                  const float* __restrict__ bias) {
    __shared__ __align__(16) float As[16][128];
    __shared__ __align__(16) float Bs[16][128];
    const int K = NI;       // 784 = 49 * 16
    const int N = NH;       // 1024

    int tid = threadIdx.x;
    int bn  = blockIdx.x;   // 0..7
    int bm  = blockIdx.y;   // 0..399

    int lrow = tid >> 1;          // 0..127
    int lcol = (tid & 1) << 3;    // 0 or 8

    const float* aptr = X  + (size_t)(bm * 128 + lrow) * K + lcol;
    const float* bptr = W1 + (size_t)(bn * 128 + lrow) * K + lcol;

    int ty = tid >> 4;   // 0..15
    int tx = tid & 15;   // 0..15

    // accp[ip][j]: lanes = (row pair) x col j.
    // ip 0..1 -> rows ty*4 + {0,1},{2,3};  ip 2..3 -> rows ty*4+64 + {0,1},{2,3}
    ull accp[4][8];
#pragma unroll
    for (int ip = 0; ip < 4; ip++)
#pragma unroll
        for (int j = 0; j < 8; j++) accp[ip][j] = 0ULL;

    // prefetch first tile
    float4 a0 = *(const float4*)(aptr);
    float4 a1 = *(const float4*)(aptr + 4);
    float4 b0 = *(const float4*)(bptr);
    float4 b1 = *(const float4*)(bptr + 4);

    for (int k0 = 0; k0 < K; k0 += 16) {
        __syncthreads();
        As[lcol + 0][lrow] = a0.x; As[lcol + 1][lrow] = a0.y;
        As[lcol + 2][lrow] = a0.z; As[lcol + 3][lrow] = a0.w;
        As[lcol + 4][lrow] = a1.x; As[lcol + 5][lrow] = a1.y;
        As[lcol + 6][lrow] = a1.z; As[lcol + 7][lrow] = a1.w;
        Bs[lcol + 0][lrow] = b0.x; Bs[lcol + 1][lrow] = b0.y;
        Bs[lcol + 2][lrow] = b0.z; Bs[lcol + 3][lrow] = b0.w;
        Bs[lcol + 4][lrow] = b1.x; Bs[lcol + 5][lrow] = b1.y;
        Bs[lcol + 6][lrow] = b1.z; Bs[lcol + 7][lrow] = b1.w;
        __syncthreads();

        if (k0 + 16 < K) {   // prefetch next tile (overlaps with FMAs below)
            a0 = *(const float4*)(aptr + k0 + 16);
            a1 = *(const float4*)(aptr + k0 + 20);
            b0 = *(const float4*)(bptr + k0 + 16);
            b1 = *(const float4*)(bptr + k0 + 20);
        }

#pragma unroll
        for (int kk = 0; kk < 16; kk++) {
            // A row pairs as b64 (little-endian: low lane = lower row)
            ulonglong2 apA = *(const ulonglong2*)&As[kk][ty * 4];
            ulonglong2 apB = *(const ulonglong2*)&As[kk][ty * 4 + 64];
            ull ap[4] = {apA.x, apA.y, apB.x, apB.y};

            float4 bA = *(const float4*)&Bs[kk][tx * 4];
            float4 bB = *(const float4*)&Bs[kk][tx * 4 + 64];
            ull bd[8] = {dup2(bA.x), dup2(bA.y), dup2(bA.z), dup2(bA.w),
                         dup2(bB.x), dup2(bB.y), dup2(bB.z), dup2(bB.w)};
#pragma unroll
            for (int ip = 0; ip < 4; ip++)
#pragma unroll
                for (int j = 0; j < 8; j++)
                    ffma2(accp[ip][j], ap[ip], bd[j]);
        }
    }

    // Epilogue: rows = bm*128 + {ty*4+i, ty*4+64+i}, cols = bn*128 + {tx*4+j, tx*4+64+j}
    int crow0 = bm * 128 + ty * 4;
    int ccol0 = bn * 128 + tx * 4;
    float4 bs0 = *(const float4*)(bias + ccol0);
    float4 bs1 = *(const float4*)(bias + ccol0 + 64);

#pragma unroll
    for (int grp = 0; grp < 2; grp++) {          // 0: rows +0..3, 1: rows +64..67
        const int rbase = crow0 + grp * 64;
#pragma unroll
        for (int ip = 0; ip < 2; ip++) {         // row pair within group
            float2 f[8];
#pragma unroll
            for (int j = 0; j < 8; j++)
                f[j] = *(float2*)&accp[grp * 2 + ip][j];

            float* r0 = g_cur1 + (size_t)(rbase + 2 * ip)     * N + ccol0;
            float* r1 = g_cur1 + (size_t)(rbase + 2 * ip + 1) * N + ccol0;
            float4 v;
            v.x = f[0].x + bs0.x; v.y = f[1].x + bs0.y;
            v.z = f[2].x + bs0.z; v.w = f[3].x + bs0.w;
            *(float4*)(r0) = v;
            v.x = f[4].x + bs1.x; v.y = f[5].x + bs1.y;
            v.z = f[6].x + bs1.z; v.w = f[7].x + bs1.w;
            *(float4*)(r0 + 64) = v;
            v.x = f[0].y + bs0.x; v.y = f[1].y + bs0.y;
            v.z = f[2].y + bs0.z; v.w = f[3].y + bs0.w;
            *(float4*)(r1) = v;
            v.x = f[4].y + bs1.x; v.y = f[5].y + bs1.y;
            v.z = f[6].y + bs1.z; v.w = f[7].y + bs1.w;
            *(float4*)(r1 + 64) = v;
        }
    }
}

// ---------------------------------------------------------------------------
// Kernel B: layer-1 leaky scan, 4 neurons per thread (float4/uchar4).
// ---------------------------------------------------------------------------
__global__ __launch_bounds__(256) void k_scan1() {
    int i4 = blockIdx.x * blockDim.x + threadIdx.x;   // 0 .. B*NH/4-1
    const size_t stride = (size_t)BATCH * NH;
    float m0 = 0.0f, m1 = 0.0f, m2 = 0.0f, m3 = 0.0f;
    for (int t = 0; t < T_STEPS; t++) {
        float4 c = *(const float4*)(g_cur1 + (size_t)t * stride + (size_t)i4 * 4);
        m0 = 0.9f * m0 + c.x - ((m0 > 1.0f) ? 1.0f : 0.0f);
        m1 = 0.9f * m1 + c.y - ((m1 > 1.0f) ? 1.0f : 0.0f);
        m2 = 0.9f * m2 + c.z - ((m2 > 1.0f) ? 1.0f : 0.0f);
        m3 = 0.9f * m3 + c.w - ((m3 > 1.0f) ? 1.0f : 0.0f);
        uchar4 s;
        s.x = (m0 > 1.0f) ? 1 : 0;
        s.y = (m1 > 1.0f) ? 1 : 0;
        s.z = (m2 > 1.0f) ? 1 : 0;
        s.w = (m3 > 1.0f) ? 1 : 0;
        *(uchar4*)(g_spk1 + (size_t)t * stride + (size_t)i4 * 4) = s;
    }
}

// ---------------------------------------------------------------------------
// Kernel C: cur2[tb,j] = sum_n spk1[tb,n]*W2[j,n] + b2[j]
// ---------------------------------------------------------------------------
__global__ __launch_bounds__(128) void k_gemm2(const float* __restrict__ W2,
                                               const float* __restrict__ b2) {
    __shared__ float         w2s[NO * NH];        // 40960 B
    __shared__ unsigned char sp[128 * 36];        // 128 rows, 32B + 4B pad

    int tid = threadIdx.x;
    int tb0 = blockIdx.x * 128;

    const float4* w2g = (const float4*)W2;
    float4* w2s4 = (float4*)w2s;
#pragma unroll
    for (int i = tid; i < (NO * NH) / 4; i += 128) w2s4[i] = w2g[i];

    float acc[NO];
#pragma unroll
    for (int j = 0; j < NO; j++) acc[j] = 0.0f;

    for (int kc = 0; kc < NH / 32; kc++) {   // 32 chunks of 32 n
        __syncthreads();
#pragma unroll
        for (int i = 0; i < 8; i++) {
            int lin = i * 128 + tid;
            int r = lin >> 3;
            int c = lin & 7;
            uint32_t v = *(const uint32_t*)(g_spk1 + (size_t)(tb0 + r) * NH + kc * 32 + c * 4);
            *(uint32_t*)(sp + r * 36 + c * 4) = v;
        }
        __syncthreads();

        const uint32_t* myrow = (const uint32_t*)(sp + tid * 36);
#pragma unroll
        for (int q = 0; q < 8; q++) {
            uint32_t v = myrow[q];
            float s0 = (float)(v & 1u);
            float s1 = (float)((v >> 8) & 1u);
            float s2 = (float)((v >> 16) & 1u);
            float s3 = (float)((v >> 24) & 1u);
            int fidx = kc * 8 + q;
#pragma unroll
            for (int j = 0; j < NO; j++) {
                float4 w = ((const float4*)(w2s + j * NH))[fidx];
                acc[j] += s0 * w.x;
                acc[j] += s1 * w.y;
                acc[j] += s2 * w.z;
                acc[j] += s3 * w.w;
            }
        }
    }

#pragma unroll
    for (int j = 0; j < NO; j++)
        g_cur2[(size_t)(tb0 + tid) * NO + j] = acc[j] + __ldg(&b2[j]);
}

// ---------------------------------------------------------------------------
// Kernel D: layer-2 leaky scan; writes spk2_rec then final mem2.
// ---------------------------------------------------------------------------
__global__ __launch_bounds__(256) void k_scan2(float* __restrict__ out) {
    __shared__ float sc[25][256];
    int idx = blockIdx.x * 256 + threadIdx.x;   // 0 .. B*NO-1 (5120)
    const int stride = BATCH * NO;
    float m = 0.0f;
    for (int tc = 0; tc < 4; tc++) {
        __syncthreads();
#pragma unroll
        for (int j = 0; j < 25; j++)
            sc[j][threadIdx.x] = g_cur2[(size_t)(tc * 25 + j) * stride + idx];
        __syncthreads();
#pragma unroll
        for (int j = 0; j < 25; j++) {
            int t = tc * 25 + j;
            float c = sc[j][threadIdx.x];
            float reset = (m > 1.0f) ? 1.0f : 0.0f;
            m = 0.9f * m + c - reset;
            out[(size_t)t * stride + idx] = (m > 1.0f) ? 1.0f : 0.0f;
        }
    }
    out[(size_t)T_STEPS * stride + idx] = m;   // final mem2
}

// ---------------------------------------------------------------------------
extern "C" void kernel_launch(void* const* d_in, const int* in_sizes, int n_in,
                              void* d_out, int out_size) {
    const float* x  = (const float*)d_in[0];   // [T,B,NI]
    const float* W1 = (const float*)d_in[1];   // [NH,NI]
    const float* b1 = (const float*)d_in[2];   // [NH]
    const float* W2 = (const float*)d_in[3];   // [NO,NH]
    const float* b2 = (const float*)d_in[4];   // [NO]
    float* out = (float*)d_out;

    // A: big GEMM cur1 = x @ W1^T + b1 (fma.rn.f32x2)
    dim3 gridA(NH / 128, M_TOT / 128);         // (8, 400)
    k_gemm1<<<gridA, 256>>>(x, W1, b1);

    // B: layer-1 scan -> spikes (4 neurons/thread)
    k_scan1<<<(BATCH * NH / 4) / 256, 256>>>();

    // C: cur2 = spk1 @ W2^T + b2
    k_gemm2<<<M_TOT / 128, 128>>>(W2, b2);

    // D: layer-2 scan -> output spikes + final mem2
    k_scan2<<<(BATCH * NO) / 256, 256>>>(out);
}

// round 11
// speedup vs baseline: 2.8898x; 1.0678x over previous
#include <cuda_runtime.h>
#include <stdint.h>

// Problem dims
#define T_STEPS 100
#define BATCH   512
#define NI      784
#define NH      1024
#define NO      10
#define M_TOT   (T_STEPS * BATCH)   // 51200
#define NIT     49                   // K chunks of 16

// Scratch (static __device__ arrays: allocation-free per harness rules)
__device__ float          g_cur1[(size_t)M_TOT * NH];   // ~210 MB
__device__ unsigned char  g_spk1[(size_t)M_TOT * NH];   // ~52 MB
__device__ float          g_cur2[(size_t)M_TOT * NO];   // ~2 MB

// ---------------------------------------------------------------------------
// Kernel A: cur1[m,n] = sum_k X[m,k]*W1[n,k] + b1[n]
// Round-1 SGEMM skeleton (128x128x16, 256 thr, 8x8 microtile split 4+4) with
// DOUBLE-BUFFERED smem: per iter, STS(next tile) -> other buffer and
// LDG prefetch(tile+2) are issued BEFORE the 1024-FFMA compute block, and
// only ONE __syncthreads() per K-iter. Scalar accumulation order identical
// to round 1 -> bit-identical cur1.
// ---------------------------------------------------------------------------
__global__ __launch_bounds__(256, 2) void k_gemm1(const float* __restrict__ X,
                                                  const float* __restrict__ W1,
                                                  const float* __restrict__ bias) {
    __shared__ __align__(16) float As[2][16][128];
    __shared__ __align__(16) float Bs[2][16][128];
    const int K = NI;       // 784 = 49 * 16
    const int N = NH;       // 1024

    int tid = threadIdx.x;
    int bn  = blockIdx.x;   // 0..7
    int bm  = blockIdx.y;   // 0..399

    int lrow = tid >> 1;          // 0..127
    int lcol = (tid & 1) << 3;    // 0 or 8

    const float* aptr = X  + (size_t)(bm * 128 + lrow) * K + lcol;
    const float* bptr = W1 + (size_t)(bn * 128 + lrow) * K + lcol;

    int ty = tid >> 4;   // 0..15
    int tx = tid & 15;   // 0..15

    float acc[8][8];
#pragma unroll
    for (int i = 0; i < 8; i++)
#pragma unroll
        for (int j = 0; j < 8; j++) acc[i][j] = 0.0f;

    float4 a0, a1, b0, b1;

    // ---- prologue: tile 0 -> regs -> buf 0 ----
    a0 = *(const float4*)(aptr);
    a1 = *(const float4*)(aptr + 4);
    b0 = *(const float4*)(bptr);
    b1 = *(const float4*)(bptr + 4);
    As[0][lcol + 0][lrow] = a0.x; As[0][lcol + 1][lrow] = a0.y;
    As[0][lcol + 2][lrow] = a0.z; As[0][lcol + 3][lrow] = a0.w;
    As[0][lcol + 4][lrow] = a1.x; As[0][lcol + 5][lrow] = a1.y;
    As[0][lcol + 6][lrow] = a1.z; As[0][lcol + 7][lrow] = a1.w;
    Bs[0][lcol + 0][lrow] = b0.x; Bs[0][lcol + 1][lrow] = b0.y;
    Bs[0][lcol + 2][lrow] = b0.z; Bs[0][lcol + 3][lrow] = b0.w;
    Bs[0][lcol + 4][lrow] = b1.x; Bs[0][lcol + 5][lrow] = b1.y;
    Bs[0][lcol + 6][lrow] = b1.z; Bs[0][lcol + 7][lrow] = b1.w;
    // prefetch tile 1 into regs
    a0 = *(const float4*)(aptr + 16);
    a1 = *(const float4*)(aptr + 20);
    b0 = *(const float4*)(bptr + 16);
    b1 = *(const float4*)(bptr + 20);
    __syncthreads();

    for (int it = 0; it < NIT; it++) {
        const int buf = it & 1;
        const int nbuf = buf ^ 1;

        // ---- STS tile(it+1) into the other buffer (no sync needed: that
        //      buffer's readers finished before the sync ending iter it-1) ----
        if (it + 1 < NIT) {
            As[nbuf][lcol + 0][lrow] = a0.x; As[nbuf][lcol + 1][lrow] = a0.y;
            As[nbuf][lcol + 2][lrow] = a0.z; As[nbuf][lcol + 3][lrow] = a0.w;
            As[nbuf][lcol + 4][lrow] = a1.x; As[nbuf][lcol + 5][lrow] = a1.y;
            As[nbuf][lcol + 6][lrow] = a1.z; As[nbuf][lcol + 7][lrow] = a1.w;
            Bs[nbuf][lcol + 0][lrow] = b0.x; Bs[nbuf][lcol + 1][lrow] = b0.y;
            Bs[nbuf][lcol + 2][lrow] = b0.z; Bs[nbuf][lcol + 3][lrow] = b0.w;
            Bs[nbuf][lcol + 4][lrow] = b1.x; Bs[nbuf][lcol + 5][lrow] = b1.y;
            Bs[nbuf][lcol + 6][lrow] = b1.z; Bs[nbuf][lcol + 7][lrow] = b1.w;
        }
        // ---- LDG prefetch tile(it+2) (latency hidden under compute) ----
        if (it + 2 < NIT) {
            const int kf = (it + 2) * 16;
            a0 = *(const float4*)(aptr + kf);
            a1 = *(const float4*)(aptr + kf + 4);
            b0 = *(const float4*)(bptr + kf);
            b1 = *(const float4*)(bptr + kf + 4);
        }

        // ---- compute from current buffer (identical order to round 1) ----
#pragma unroll
        for (int kk = 0; kk < 16; kk++) {
            float4 aA = *(const float4*)&As[buf][kk][ty * 4];
            float4 aB = *(const float4*)&As[buf][kk][ty * 4 + 64];
            float4 bA = *(const float4*)&Bs[buf][kk][tx * 4];
            float4 bB = *(const float4*)&Bs[buf][kk][tx * 4 + 64];
            float av[8] = {aA.x, aA.y, aA.z, aA.w, aB.x, aB.y, aB.z, aB.w};
            float bv[8] = {bA.x, bA.y, bA.z, bA.w, bB.x, bB.y, bB.z, bB.w};
#pragma unroll
            for (int i = 0; i < 8; i++)
#pragma unroll
                for (int j = 0; j < 8; j++)
                    acc[i][j] += av[i] * bv[j];
        }
        __syncthreads();
    }

    // Epilogue: rows = bm*128 + {ty*4+i, ty*4+64+i}, cols = bn*128 + {tx*4+j, tx*4+64+j}
    int crow0 = bm * 128 + ty * 4;
    int ccol0 = bn * 128 + tx * 4;
    float4 bs0 = *(const float4*)(bias + ccol0);
    float4 bs1 = *(const float4*)(bias + ccol0 + 64);

#pragma unroll
    for (int i = 0; i < 4; i++) {
        float* c0 = g_cur1 + (size_t)(crow0 + i) * N + ccol0;
        float4 v;
        v.x = acc[i][0] + bs0.x; v.y = acc[i][1] + bs0.y;
        v.z = acc[i][2] + bs0.z; v.w = acc[i][3] + bs0.w;
        *(float4*)(c0) = v;
        v.x = acc[i][4] + bs1.x; v.y = acc[i][5] + bs1.y;
        v.z = acc[i][6] + bs1.z; v.w = acc[i][7] + bs1.w;
        *(float4*)(c0 + 64) = v;

        float* c1 = g_cur1 + (size_t)(crow0 + 64 + i) * N + ccol0;
        v.x = acc[4 + i][0] + bs0.x; v.y = acc[4 + i][1] + bs0.y;
        v.z = acc[4 + i][2] + bs0.z; v.w = acc[4 + i][3] + bs0.w;
        *(float4*)(c1) = v;
        v.x = acc[4 + i][4] + bs1.x; v.y = acc[4 + i][5] + bs1.y;
        v.z = acc[4 + i][6] + bs1.z; v.w = acc[4 + i][7] + bs1.w;
        *(float4*)(c1 + 64) = v;
    }
}

// ---------------------------------------------------------------------------
// Kernel B: layer-1 leaky scan, 4 neurons per thread (float4/uchar4).
// ---------------------------------------------------------------------------
__global__ __launch_bounds__(256) void k_scan1() {
    int i4 = blockIdx.x * blockDim.x + threadIdx.x;   // 0 .. B*NH/4-1
    const size_t stride = (size_t)BATCH * NH;
    float m0 = 0.0f, m1 = 0.0f, m2 = 0.0f, m3 = 0.0f;
    for (int t = 0; t < T_STEPS; t++) {
        float4 c = *(const float4*)(g_cur1 + (size_t)t * stride + (size_t)i4 * 4);
        m0 = 0.9f * m0 + c.x - ((m0 > 1.0f) ? 1.0f : 0.0f);
        m1 = 0.9f * m1 + c.y - ((m1 > 1.0f) ? 1.0f : 0.0f);
        m2 = 0.9f * m2 + c.z - ((m2 > 1.0f) ? 1.0f : 0.0f);
        m3 = 0.9f * m3 + c.w - ((m3 > 1.0f) ? 1.0f : 0.0f);
        uchar4 s;
        s.x = (m0 > 1.0f) ? 1 : 0;
        s.y = (m1 > 1.0f) ? 1 : 0;
        s.z = (m2 > 1.0f) ? 1 : 0;
        s.w = (m3 > 1.0f) ? 1 : 0;
        *(uchar4*)(g_spk1 + (size_t)t * stride + (size_t)i4 * 4) = s;
    }
}

// ---------------------------------------------------------------------------
// Kernel C: cur2[tb,j] = sum_n spk1[tb,n]*W2[j,n] + b2[j]
// ---------------------------------------------------------------------------
__global__ __launch_bounds__(128) void k_gemm2(const float* __restrict__ W2,
                                               const float* __restrict__ b2) {
    __shared__ float         w2s[NO * NH];        // 40960 B
    __shared__ unsigned char sp[128 * 36];        // 128 rows, 32B + 4B pad

    int tid = threadIdx.x;
    int tb0 = blockIdx.x * 128;

    const float4* w2g = (const float4*)W2;
    float4* w2s4 = (float4*)w2s;
#pragma unroll
    for (int i = tid; i < (NO * NH) / 4; i += 128) w2s4[i] = w2g[i];

    float acc[NO];
#pragma unroll
    for (int j = 0; j < NO; j++) acc[j] = 0.0f;

    for (int kc = 0; kc < NH / 32; kc++) {   // 32 chunks of 32 n
        __syncthreads();
#pragma unroll
        for (int i = 0; i < 8; i++) {
            int lin = i * 128 + tid;
            int r = lin >> 3;
            int c = lin & 7;
            uint32_t v = *(const uint32_t*)(g_spk1 + (size_t)(tb0 + r) * NH + kc * 32 + c * 4);
            *(uint32_t*)(sp + r * 36 + c * 4) = v;
        }
        __syncthreads();

        const uint32_t* myrow = (const uint32_t*)(sp + tid * 36);
#pragma unroll
        for (int q = 0; q < 8; q++) {
            uint32_t v = myrow[q];
            float s0 = (float)(v & 1u);
            float s1 = (float)((v >> 8) & 1u);
            float s2 = (float)((v >> 16) & 1u);
            float s3 = (float)((v >> 24) & 1u);
            int fidx = kc * 8 + q;
#pragma unroll
            for (int j = 0; j < NO; j++) {
                float4 w = ((const float4*)(w2s + j * NH))[fidx];
                acc[j] += s0 * w.x;
                acc[j] += s1 * w.y;
                acc[j] += s2 * w.z;
                acc[j] += s3 * w.w;
            }
        }
    }

#pragma unroll
    for (int j = 0; j < NO; j++)
        g_cur2[(size_t)(tb0 + tid) * NO + j] = acc[j] + __ldg(&b2[j]);
}

// ---------------------------------------------------------------------------
// Kernel D: layer-2 leaky scan; writes spk2_rec then final mem2.
// ---------------------------------------------------------------------------
__global__ __launch_bounds__(256) void k_scan2(float* __restrict__ out) {
    __shared__ float sc[25][256];
    int idx = blockIdx.x * 256 + threadIdx.x;   // 0 .. B*NO-1 (5120)
    const int stride = BATCH * NO;
    float m = 0.0f;
    for (int tc = 0; tc < 4; tc++) {
        __syncthreads();
#pragma unroll
        for (int j = 0; j < 25; j++)
            sc[j][threadIdx.x] = g_cur2[(size_t)(tc * 25 + j) * stride + idx];
        __syncthreads();
#pragma unroll
        for (int j = 0; j < 25; j++) {
            int t = tc * 25 + j;
            float c = sc[j][threadIdx.x];
            float reset = (m > 1.0f) ? 1.0f : 0.0f;
            m = 0.9f * m + c - reset;
            out[(size_t)t * stride + idx] = (m > 1.0f) ? 1.0f : 0.0f;
        }
    }
    out[(size_t)T_STEPS * stride + idx] = m;   // final mem2
}

// ---------------------------------------------------------------------------
extern "C" void kernel_launch(void* const* d_in, const int* in_sizes, int n_in,
                              void* d_out, int out_size) {
    const float* x  = (const float*)d_in[0];   // [T,B,NI]
    const float* W1 = (const float*)d_in[1];   // [NH,NI]
    const float* b1 = (const float*)d_in[2];   // [NH]
    const float* W2 = (const float*)d_in[3];   // [NO,NH]
    const float* b2 = (const float*)d_in[4];   // [NO]
    float* out = (float*)d_out;

    // A: big GEMM cur1 = x @ W1^T + b1 (double-buffered FFMA)
    dim3 gridA(NH / 128, M_TOT / 128);         // (8, 400)
    k_gemm1<<<gridA, 256>>>(x, W1, b1);

    // B: layer-1 scan -> spikes (4 neurons/thread)
    k_scan1<<<(BATCH * NH / 4) / 256, 256>>>();

    // C: cur2 = spk1 @ W2^T + b2
    k_gemm2<<<M_TOT / 128, 128>>>(W2, b2);

    // D: layer-2 scan -> output spikes + final mem2
    k_scan2<<<(BATCH * NO) / 256, 256>>>(out);
}